// round 6
// baseline (speedup 1.0000x reference)
#include <cuda_runtime.h>
#include <cuda_bf16.h>
#include <cstdint>

#define NU 100000
#define NM 20000
#define DD 128
#define EE 1000000
#define CAPU 96    // >10 sigma above Poisson(10) max over 100k draws
#define CAPM 256   // >10 sigma above Poisson(50) max over 20k draws

// ---------------- scratch (static device globals; no runtime alloc) --------
__device__ float4 g_agg_u[NU * 32];
__device__ float4 g_agg_m[NM * 32];
__device__ float4 g_r_u[NU * 32];
__device__ float4 g_r_m[NM * 32];
__device__ int    g_deg_u[NU];
__device__ int    g_deg_m[NM];
__device__ int    g_csr_u[(size_t)NU * CAPU];
__device__ int    g_csr_m[(size_t)NM * CAPM];
// Pre-built mma B fragments: [matrix][hi=0/lo=1][kc 0..7][ntile 0..15][lane 0..31]
// frag.x = {W[k0][n], W[k0+1][n]}, frag.y = {W[k0+8][n], W[k0+9][n]} (bf16x2),
// with n = ntile*8 + lane/4, k0 = kc*16 + (lane%4)*2   (canonical m16n8k16 B).
__device__ uint2 g_Bfrag[8][2][8][16][32];

// ---------------- helpers ---------------------------------------------------
__device__ __forceinline__ uint32_t smem_u32(const void* p) {
    uint32_t a;
    asm("{ .reg .u64 t; cvta.to.shared.u64 t, %1; cvt.u32.u64 %0, t; }" : "=r"(a) : "l"(p));
    return a;
}
// pack {lo half = a, hi half = b}
__device__ __forceinline__ uint32_t pk_bf16x2(float a, float b) {
    uint32_t r;
    asm("cvt.rn.bf16x2.f32 %0, %1, %2;" : "=r"(r) : "f"(b), "f"(a));
    return r;
}
__device__ __forceinline__ void ldm4(uint32_t* r, uint32_t addr) {
    asm volatile("ldmatrix.sync.aligned.m8n8.x4.shared.b16 {%0,%1,%2,%3}, [%4];"
                 : "=r"(r[0]), "=r"(r[1]), "=r"(r[2]), "=r"(r[3]) : "r"(addr));
}
__device__ __forceinline__ void mma16816(float* c, const uint32_t* a, uint32_t b0, uint32_t b1) {
    asm volatile("mma.sync.aligned.m16n8k16.row.col.f32.bf16.bf16.f32 "
                 "{%0,%1,%2,%3}, {%4,%5,%6,%7}, {%8,%9}, {%0,%1,%2,%3};"
                 : "+f"(c[0]), "+f"(c[1]), "+f"(c[2]), "+f"(c[3])
                 : "r"(a[0]), "r"(a[1]), "r"(a[2]), "r"(a[3]), "r"(b0), "r"(b1));
}
// swizzle for 256B rows: XOR 16B-chunk bits [4:7) with (row & 7)
__device__ __forceinline__ uint32_t swz(uint32_t off) { return off ^ ((off >> 4) & 0x70u); }

// ---------------- CSR build --------------------------------------------------
__global__ __launch_bounds__(256) void build_kernel(
    const int* __restrict__ src, const int* __restrict__ dst)
{
    int e = blockIdx.x * 256 + threadIdx.x;
    if (e >= EE) return;
    int s = __ldg(src + e);
    int d = __ldg(dst + e);
    int pm = atomicAdd(&g_deg_m[d], 1);
    if (pm < CAPM) g_csr_m[(size_t)d * CAPM + pm] = s;
    int pu = atomicAdd(&g_deg_u[s], 1);
    if (pu < CAPU) g_csr_u[(size_t)s * CAPU + pu] = d;
}

// ---------------- gather (one warp per node, mean of neighbor rows) ---------
__global__ __launch_bounds__(256) void gather_kernel(
    const float4* __restrict__ xu, const float4* __restrict__ xm)
{
    const int lane = threadIdx.x & 31;
    const int w = (blockIdx.x * 256 + threadIdx.x) >> 5;

    const int* csr;
    const float4* src;
    float4* out;
    int deg;
    if (w < NU) {
        deg = min(__ldg(&g_deg_u[w]), CAPU);
        csr = &g_csr_u[(size_t)w * CAPU];
        src = xm;
        out = &g_agg_u[(size_t)w * 32];
    } else {
        int n = w - NU;
        if (n >= NM) return;
        deg = min(__ldg(&g_deg_m[n]), CAPM);
        csr = &g_csr_m[(size_t)n * CAPM];
        src = xu;
        out = &g_agg_m[(size_t)n * 32];
    }

    float4 a0 = make_float4(0.f, 0.f, 0.f, 0.f);
    float4 a1 = make_float4(0.f, 0.f, 0.f, 0.f);

    for (int i = 0; i < deg; i += 32) {
        int idx = (i + lane < deg) ? __ldg(csr + i + lane) : 0;
        int cnt = min(32, deg - i);
        if (cnt == 32) {
#pragma unroll
            for (int j = 0; j < 32; j += 2) {
                int i0 = __shfl_sync(0xffffffffu, idx, j);
                int i1 = __shfl_sync(0xffffffffu, idx, j + 1);
                float4 v0 = __ldg(&src[(size_t)i0 * 32 + lane]);
                float4 v1 = __ldg(&src[(size_t)i1 * 32 + lane]);
                a0.x += v0.x; a0.y += v0.y; a0.z += v0.z; a0.w += v0.w;
                a1.x += v1.x; a1.y += v1.y; a1.z += v1.z; a1.w += v1.w;
            }
        } else {
            for (int j = 0; j < cnt; j++) {
                int id = __shfl_sync(0xffffffffu, idx, j);
                float4 v = __ldg(&src[(size_t)id * 32 + lane]);
                a0.x += v.x; a0.y += v.y; a0.z += v.z; a0.w += v.w;
            }
        }
    }
    float inv = 1.f / (float)max(deg, 1);
    float4 r;
    r.x = (a0.x + a1.x) * inv;
    r.y = (a0.y + a1.y) * inv;
    r.z = (a0.z + a1.z) * inv;
    r.w = (a0.w + a1.w) * inv;
    out[lane] = r;
}

// ---------------- weight prep: canonical B fragments, bf16 hi/lo split ------
__global__ __launch_bounds__(256) void prep_kernel(
    const float* __restrict__ W0, const float* __restrict__ W1,
    const float* __restrict__ W2, const float* __restrict__ W3,
    const float* __restrict__ W4, const float* __restrict__ W5,
    const float* __restrict__ W6, const float* __restrict__ W7)
{
    const float* Ws[8] = {W0, W1, W2, W3, W4, W5, W6, W7};
    int m = blockIdx.x;
    const float* W = Ws[m];
    for (int idx = threadIdx.x; idx < 4096; idx += 256) {
        int kc = idx >> 9;
        int t = (idx >> 5) & 15;
        int lane = idx & 31;
        int n = t * 8 + (lane >> 2);
        int k0 = kc * 16 + (lane & 3) * 2;
        float w00 = __ldg(&W[(size_t)k0 * 128 + n]);
        float w01 = __ldg(&W[(size_t)(k0 + 1) * 128 + n]);
        float w10 = __ldg(&W[(size_t)(k0 + 8) * 128 + n]);
        float w11 = __ldg(&W[(size_t)(k0 + 9) * 128 + n]);
        uint32_t h0 = pk_bf16x2(w00, w01);
        uint32_t h1 = pk_bf16x2(w10, w11);
        uint32_t l0 = pk_bf16x2(w00 - __uint_as_float(h0 << 16), w01 - __uint_as_float(h0 & 0xFFFF0000u));
        uint32_t l1 = pk_bf16x2(w10 - __uint_as_float(h1 << 16), w11 - __uint_as_float(h1 & 0xFFFF0000u));
        g_Bfrag[m][0][kc][t][lane] = make_uint2(h0, h1);
        g_Bfrag[m][1][kc][t][lane] = make_uint2(l0, l1);
    }
}

// ---------------- tensor GEMM (mma.sync bf16, 3-term split) -----------------
// Per 128-row CTA: D = agg @ Wl + x @ Wr; epilogue bias (+relu+residual).
// A (both passes, hi/lo) staged once into smem; B fragments streamed from
// global with one-iteration prefetch; single __syncthreads in the kernel.
#define SM_BIAS 0
#define SM_A    1024
#define SM_TOTAL (1024 + 4 * 32768)

__global__ __launch_bounds__(256, 1) void tgemm_kernel(
    const float* __restrict__ x_u, const float* __restrict__ x_m,
    const float* __restrict__ b_mu, const float* __restrict__ b_um,
    float* __restrict__ out_u, float* __restrict__ out_m,
    int gb_u, int mode, int layer)
{
    extern __shared__ char smem[];
    const uint32_t sb = smem_u32(smem);
    const int tid = threadIdx.x;
    const int wid = tid >> 5;
    const int lane = tid & 31;

    const bool user = (int)blockIdx.x < gb_u;
    const int  base = (user ? blockIdx.x : blockIdx.x - gb_u) * 128;
    const int  M    = user ? NU : NM;
    const float* xA  = user ? x_u : x_m;
    const float* agg = user ? (const float*)g_agg_u : (const float*)g_agg_m;
    const float* bias = user ? b_mu : b_um;
    float* out = user ? out_u : out_m;
    const int wl_idx = (user ? 2 : 0) + 4 * layer;
    const int wr_idx = wl_idx + 1;

    float* bsm = (float*)(smem + SM_BIAS);
    if (tid < 128) bsm[tid] = __ldg(&bias[tid]);

    const int wm = wid & 3, wn = wid >> 2;

    // ---- stage A (both passes) as bf16 hi/lo into smem ----
    for (int g = tid; g < 4096; g += 256) {
        int pass = g >> 11;
        int rem = g & 2047;
        int row = rem >> 4;
        int k = (rem & 15) * 8;
        int grow = base + row;
        if (grow > M - 1) grow = M - 1;
        const float* A = pass ? xA : agg;
        const float4* src = (const float4*)&A[(size_t)grow * 128 + k];
        float4 v0 = __ldg(src), v1 = __ldg(src + 1);
        uint4 hi, lo;
        hi.x = pk_bf16x2(v0.x, v0.y);
        hi.y = pk_bf16x2(v0.z, v0.w);
        hi.z = pk_bf16x2(v1.x, v1.y);
        hi.w = pk_bf16x2(v1.z, v1.w);
        lo.x = pk_bf16x2(v0.x - __uint_as_float(hi.x << 16), v0.y - __uint_as_float(hi.x & 0xFFFF0000u));
        lo.y = pk_bf16x2(v0.z - __uint_as_float(hi.y << 16), v0.w - __uint_as_float(hi.y & 0xFFFF0000u));
        lo.z = pk_bf16x2(v1.x - __uint_as_float(hi.z << 16), v1.y - __uint_as_float(hi.z & 0xFFFF0000u));
        lo.w = pk_bf16x2(v1.z - __uint_as_float(hi.w << 16), v1.w - __uint_as_float(hi.w & 0xFFFF0000u));
        uint32_t so = swz((uint32_t)row * 256u + (uint32_t)k * 2u);
        uint32_t bufb = SM_A + (uint32_t)pass * 65536u;
        *(uint4*)(smem + bufb + so) = hi;
        *(uint4*)(smem + bufb + 32768 + so) = lo;
    }

    // per-lane ldmatrix A offsets (within one 32KB tile, pre-swizzle)
    const int a_row = (lane & 7) + ((lane >> 3) & 1) * 8;
    const int a_kh  = ((lane >> 4) & 1) * 8;
    uint32_t aoff[2];
#pragma unroll
    for (int tm = 0; tm < 2; tm++)
        aoff[tm] = (uint32_t)(wm * 32 + tm * 16 + a_row) * 256u + (uint32_t)a_kh * 2u;

    float acc[2][8][4];
#pragma unroll
    for (int i = 0; i < 2; i++)
#pragma unroll
        for (int j = 0; j < 8; j++)
#pragma unroll
            for (int q = 0; q < 4; q++) acc[i][j][q] = 0.f;

    __syncthreads();   // A staged, bias ready

    // ---- MMA mainloop: 16 iterations (pass, kc), B prefetched 1 ahead ----
    uint2 bh[8], bl[8];
    {
        const uint2* ph = &g_Bfrag[wl_idx][0][0][wn * 8][lane];
        const uint2* pl = &g_Bfrag[wl_idx][1][0][wn * 8][lane];
#pragma unroll
        for (int t = 0; t < 8; t++) { bh[t] = __ldg(ph + t * 32); bl[t] = __ldg(pl + t * 32); }
    }

    for (int it = 0; it < 16; it++) {
        const int pass = it >> 3, kc = it & 7;
        const uint32_t abase = sb + SM_A + (uint32_t)pass * 65536u;

        uint32_t ah[2][4], al[2][4];
#pragma unroll
        for (int tm = 0; tm < 2; tm++) {
            uint32_t so = swz(aoff[tm] + (uint32_t)kc * 32u);
            ldm4(ah[tm], abase + so);
            ldm4(al[tm], abase + 32768 + so);
        }

        uint2 nh[8], nl[8];
        if (it < 15) {
            const int np = (it + 1) >> 3, nkc = (it + 1) & 7;
            const int widx = np ? wr_idx : wl_idx;
            const uint2* ph = &g_Bfrag[widx][0][nkc][wn * 8][lane];
            const uint2* pl = &g_Bfrag[widx][1][nkc][wn * 8][lane];
#pragma unroll
            for (int t = 0; t < 8; t++) { nh[t] = __ldg(ph + t * 32); nl[t] = __ldg(pl + t * 32); }
        }

#pragma unroll
        for (int tm = 0; tm < 2; tm++)
#pragma unroll
            for (int tn = 0; tn < 8; tn++) {
                mma16816(acc[tm][tn], ah[tm], bh[tn].x, bh[tn].y);
                mma16816(acc[tm][tn], ah[tm], bl[tn].x, bl[tn].y);
                mma16816(acc[tm][tn], al[tm], bh[tn].x, bh[tn].y);
            }

        if (it < 15) {
#pragma unroll
            for (int t = 0; t < 8; t++) { bh[t] = nh[t]; bl[t] = nl[t]; }
        }
    }

    // ---- epilogue ----
    const int gid = lane >> 2, qid = lane & 3;
#pragma unroll
    for (int tm = 0; tm < 2; tm++) {
#pragma unroll
        for (int rs = 0; rs < 2; rs++) {
            int row = base + wm * 32 + tm * 16 + gid + rs * 8;
            if (row < M) {
#pragma unroll
                for (int tn = 0; tn < 8; tn++) {
                    int col = wn * 64 + tn * 8 + qid * 2;
                    float vx = acc[tm][tn][rs * 2 + 0] + bsm[col];
                    float vy = acc[tm][tn][rs * 2 + 1] + bsm[col + 1];
                    if (mode) {
                        float2 xv = __ldg((const float2*)&xA[(size_t)row * 128 + col]);
                        vx = xv.x + fmaxf(vx, 0.f);
                        vy = xv.y + fmaxf(vy, 0.f);
                    }
                    *(float2*)&out[(size_t)row * 128 + col] = make_float2(vx, vy);
                }
            }
        }
    }
}

// ---------------- host ------------------------------------------------------
extern "C" void kernel_launch(void* const* d_in, const int* in_sizes, int n_in,
                              void* d_out, int out_size)
{
    const float* x_user = nullptr;
    const float* x_movie = nullptr;
    const int* e_src = nullptr;
    const int* e_dst = nullptr;
    const float* W[8] = {};
    const float* B[4] = {};
    int nw = 0, nb = 0;
    for (int i = 0; i < n_in; i++) {
        int sz = in_sizes[i];
        if (sz == NU * DD)      x_user = (const float*)d_in[i];
        else if (sz == NM * DD) x_movie = (const float*)d_in[i];
        else if (sz == EE)      { if (!e_src) e_src = (const int*)d_in[i]; else e_dst = (const int*)d_in[i]; }
        else if (sz == DD * DD) { if (nw < 8) W[nw++] = (const float*)d_in[i]; }
        else if (sz == DD)      { if (nb < 4) B[nb++] = (const float*)d_in[i]; }
    }
    // W order: Wl1_um, Wr1_um, Wl1_mu, Wr1_mu, Wl2_um, Wr2_um, Wl2_mu, Wr2_mu
    const float *b1_um = B[0], *b1_mu = B[1], *b2_um = B[2], *b2_mu = B[3];

    float* out = (float*)d_out;
    float *r_u, *r_m;
    int *deg_u, *deg_m;
    cudaGetSymbolAddress((void**)&r_u, g_r_u);
    cudaGetSymbolAddress((void**)&r_m, g_r_m);
    cudaGetSymbolAddress((void**)&deg_u, g_deg_u);
    cudaGetSymbolAddress((void**)&deg_m, g_deg_m);

    cudaFuncSetAttribute(tgemm_kernel, cudaFuncAttributeMaxDynamicSharedMemorySize, SM_TOTAL);

    const int gb_m = (NM + 127) / 128;
    const int gb_u = (NU + 127) / 128;
    const int gblocks = (NU + NM) / 8;          // one warp per node

    prep_kernel<<<8, 256>>>(W[0], W[1], W[2], W[3], W[4], W[5], W[6], W[7]);

    // CSR build (reused by both layers)
    cudaMemsetAsync(deg_u, 0, NU * sizeof(int));
    cudaMemsetAsync(deg_m, 0, NM * sizeof(int));
    build_kernel<<<(EE + 255) / 256, 256>>>(e_src, e_dst);

    // Layer 1
    gather_kernel<<<gblocks, 256>>>((const float4*)x_user, (const float4*)x_movie);
    tgemm_kernel<<<gb_u + gb_m, 256, SM_TOTAL>>>(x_user, x_movie, b1_mu, b1_um,
                                                 r_u, r_m, gb_u, 1, 0);

    // Layer 2
    gather_kernel<<<gblocks, 256>>>((const float4*)r_u, (const float4*)r_m);
    tgemm_kernel<<<gb_u + gb_m, 256, SM_TOTAL>>>(r_u, r_m, b2_mu, b2_um,
                                                 out, out + (size_t)NU * DD, gb_u, 0, 1);
}

// round 7
// speedup vs baseline: 1.2176x; 1.2176x over previous
#include <cuda_runtime.h>
#include <cuda_bf16.h>
#include <cstdint>

#define NU 100000
#define NM 20000
#define DD 128
#define EE 1000000
#define CAPU 96    // >10 sigma above Poisson(10) max over 100k draws
#define CAPM 256   // >10 sigma above Poisson(50) max over 20k draws

// ---------------- scratch (static device globals; no runtime alloc) --------
__device__ float4 g_agg_u[NU * 32];
__device__ float4 g_agg_m[NM * 32];
__device__ float4 g_r_u[NU * 32];
__device__ float4 g_r_m[NM * 32];
__device__ int    g_deg_u[NU];
__device__ int    g_deg_m[NM];
__device__ int    g_csr_u[(size_t)NU * CAPU];
__device__ int    g_csr_m[(size_t)NM * CAPM];
// Pre-built mma B fragments: [matrix][hi=0/lo=1][kc 0..7][ntile 0..15][lane 0..31]
// frag.x = {W[k0][n], W[k0+1][n]}, frag.y = {W[k0+8][n], W[k0+9][n]} (bf16x2),
// with n = ntile*8 + lane/4, k0 = kc*16 + (lane%4)*2   (canonical m16n8k16 B).
__device__ uint2 g_Bfrag[8][2][8][16][32];

// ---------------- helpers ---------------------------------------------------
__device__ __forceinline__ uint32_t smem_u32(const void* p) {
    uint32_t a;
    asm("{ .reg .u64 t; cvta.to.shared.u64 t, %1; cvt.u32.u64 %0, t; }" : "=r"(a) : "l"(p));
    return a;
}
// pack {lo half = a, hi half = b}
__device__ __forceinline__ uint32_t pk_bf16x2(float a, float b) {
    uint32_t r;
    asm("cvt.rn.bf16x2.f32 %0, %1, %2;" : "=r"(r) : "f"(b), "f"(a));
    return r;
}
__device__ __forceinline__ void ldm4(uint32_t* r, uint32_t addr) {
    asm volatile("ldmatrix.sync.aligned.m8n8.x4.shared.b16 {%0,%1,%2,%3}, [%4];"
                 : "=r"(r[0]), "=r"(r[1]), "=r"(r[2]), "=r"(r[3]) : "r"(addr));
}
__device__ __forceinline__ void mma16816(float* c, const uint32_t* a, uint32_t b0, uint32_t b1) {
    asm volatile("mma.sync.aligned.m16n8k16.row.col.f32.bf16.bf16.f32 "
                 "{%0,%1,%2,%3}, {%4,%5,%6,%7}, {%8,%9}, {%0,%1,%2,%3};"
                 : "+f"(c[0]), "+f"(c[1]), "+f"(c[2]), "+f"(c[3])
                 : "r"(a[0]), "r"(a[1]), "r"(a[2]), "r"(a[3]), "r"(b0), "r"(b1));
}
// swizzle for 256B rows: XOR 16B-chunk bits [4:7) with (row & 7)
__device__ __forceinline__ uint32_t swz(uint32_t off) { return off ^ ((off >> 4) & 0x70u); }

// ---------------- CSR build --------------------------------------------------
__global__ __launch_bounds__(256) void build_kernel(
    const int* __restrict__ src, const int* __restrict__ dst)
{
    int e = blockIdx.x * 256 + threadIdx.x;
    if (e >= EE) return;
    int s = __ldg(src + e);
    int d = __ldg(dst + e);
    int pm = atomicAdd(&g_deg_m[d], 1);
    if (pm < CAPM) g_csr_m[(size_t)d * CAPM + pm] = s;
    int pu = atomicAdd(&g_deg_u[s], 1);
    if (pu < CAPU) g_csr_u[(size_t)s * CAPU + pu] = d;
}

// ---------------- gather (one warp per node, mean of neighbor rows) ---------
__global__ __launch_bounds__(256) void gather_kernel(
    const float4* __restrict__ xu, const float4* __restrict__ xm)
{
    const int lane = threadIdx.x & 31;
    const int w = (blockIdx.x * 256 + threadIdx.x) >> 5;

    const int* csr;
    const float4* src;
    float4* out;
    int deg;
    if (w < NU) {
        deg = min(__ldg(&g_deg_u[w]), CAPU);
        csr = &g_csr_u[(size_t)w * CAPU];
        src = xm;
        out = &g_agg_u[(size_t)w * 32];
    } else {
        int n = w - NU;
        if (n >= NM) return;
        deg = min(__ldg(&g_deg_m[n]), CAPM);
        csr = &g_csr_m[(size_t)n * CAPM];
        src = xu;
        out = &g_agg_m[(size_t)n * 32];
    }

    float4 a0 = make_float4(0.f, 0.f, 0.f, 0.f);
    float4 a1 = make_float4(0.f, 0.f, 0.f, 0.f);

    for (int i = 0; i < deg; i += 32) {
        int idx = (i + lane < deg) ? __ldg(csr + i + lane) : 0;
        int cnt = min(32, deg - i);
        if (cnt == 32) {
#pragma unroll
            for (int j = 0; j < 32; j += 2) {
                int i0 = __shfl_sync(0xffffffffu, idx, j);
                int i1 = __shfl_sync(0xffffffffu, idx, j + 1);
                float4 v0 = __ldg(&src[(size_t)i0 * 32 + lane]);
                float4 v1 = __ldg(&src[(size_t)i1 * 32 + lane]);
                a0.x += v0.x; a0.y += v0.y; a0.z += v0.z; a0.w += v0.w;
                a1.x += v1.x; a1.y += v1.y; a1.z += v1.z; a1.w += v1.w;
            }
        } else {
            for (int j = 0; j < cnt; j++) {
                int id = __shfl_sync(0xffffffffu, idx, j);
                float4 v = __ldg(&src[(size_t)id * 32 + lane]);
                a0.x += v.x; a0.y += v.y; a0.z += v.z; a0.w += v.w;
            }
        }
    }
    float inv = 1.f / (float)max(deg, 1);
    float4 r;
    r.x = (a0.x + a1.x) * inv;
    r.y = (a0.y + a1.y) * inv;
    r.z = (a0.z + a1.z) * inv;
    r.w = (a0.w + a1.w) * inv;
    out[lane] = r;
}

// ---------------- weight prep: canonical B fragments, bf16 hi/lo split ------
__global__ __launch_bounds__(256) void prep_kernel(
    const float* __restrict__ W0, const float* __restrict__ W1,
    const float* __restrict__ W2, const float* __restrict__ W3,
    const float* __restrict__ W4, const float* __restrict__ W5,
    const float* __restrict__ W6, const float* __restrict__ W7)
{
    const float* Ws[8] = {W0, W1, W2, W3, W4, W5, W6, W7};
    int m = blockIdx.x;
    const float* W = Ws[m];
    for (int idx = threadIdx.x; idx < 4096; idx += 256) {
        int kc = idx >> 9;
        int t = (idx >> 5) & 15;
        int lane = idx & 31;
        int n = t * 8 + (lane >> 2);
        int k0 = kc * 16 + (lane & 3) * 2;
        float w00 = __ldg(&W[(size_t)k0 * 128 + n]);
        float w01 = __ldg(&W[(size_t)(k0 + 1) * 128 + n]);
        float w10 = __ldg(&W[(size_t)(k0 + 8) * 128 + n]);
        float w11 = __ldg(&W[(size_t)(k0 + 9) * 128 + n]);
        uint32_t h0 = pk_bf16x2(w00, w01);
        uint32_t h1 = pk_bf16x2(w10, w11);
        uint32_t l0 = pk_bf16x2(w00 - __uint_as_float(h0 << 16), w01 - __uint_as_float(h0 & 0xFFFF0000u));
        uint32_t l1 = pk_bf16x2(w10 - __uint_as_float(h1 << 16), w11 - __uint_as_float(h1 & 0xFFFF0000u));
        g_Bfrag[m][0][kc][t][lane] = make_uint2(h0, h1);
        g_Bfrag[m][1][kc][t][lane] = make_uint2(l0, l1);
    }
}

// ---------------- tensor GEMM (mma.sync bf16, 3-term split) -----------------
// Per 128-row CTA: D = agg @ Wl + x @ Wr; epilogue bias (+relu+residual).
// A staged per pass into 64KB smem (hi/lo); B fragments read straight from
// global (same addresses chip-wide -> L1/L2 broadcast). 2 CTAs/SM.
#define SM_BIAS 0
#define SM_A    1024
#define SM_TOTAL (1024 + 2 * 32768)

__global__ __launch_bounds__(256, 2) void tgemm_kernel(
    const float* __restrict__ x_u, const float* __restrict__ x_m,
    const float* __restrict__ b_mu, const float* __restrict__ b_um,
    float* __restrict__ out_u, float* __restrict__ out_m,
    int gb_u, int mode, int layer)
{
    extern __shared__ char smem[];
    const uint32_t sb = smem_u32(smem);
    const int tid = threadIdx.x;
    const int wid = tid >> 5;
    const int lane = tid & 31;

    const bool user = (int)blockIdx.x < gb_u;
    const int  base = (user ? blockIdx.x : blockIdx.x - gb_u) * 128;
    const int  M    = user ? NU : NM;
    const float* xA  = user ? x_u : x_m;
    const float* agg = user ? (const float*)g_agg_u : (const float*)g_agg_m;
    const float* bias = user ? b_mu : b_um;
    float* out = user ? out_u : out_m;
    const int wl_idx = (user ? 2 : 0) + 4 * layer;
    const int wr_idx = wl_idx + 1;

    float* bsm = (float*)(smem + SM_BIAS);
    if (tid < 128) bsm[tid] = __ldg(&bias[tid]);

    const int wm = wid & 3, wn = wid >> 2;

    // per-lane ldmatrix A offsets (within one 32KB tile, pre-swizzle)
    const int a_row = (lane & 7) + ((lane >> 3) & 1) * 8;
    const int a_kh  = ((lane >> 4) & 1) * 8;
    uint32_t aoff[2];
#pragma unroll
    for (int tm = 0; tm < 2; tm++)
        aoff[tm] = (uint32_t)(wm * 32 + tm * 16 + a_row) * 256u + (uint32_t)a_kh * 2u;

    float acc[2][8][4];
#pragma unroll
    for (int i = 0; i < 2; i++)
#pragma unroll
        for (int j = 0; j < 8; j++)
#pragma unroll
            for (int q = 0; q < 4; q++) acc[i][j][q] = 0.f;

    for (int pass = 0; pass < 2; pass++) {
        __syncthreads();   // smem A free for reuse (and bias ready on pass 0)

        // ---- stage A(pass) as bf16 hi/lo ----
        const float* A = pass ? xA : agg;
        for (int g = tid; g < 2048; g += 256) {
            int row = g >> 4;
            int k = (g & 15) * 8;
            int grow = base + row;
            if (grow > M - 1) grow = M - 1;
            const float4* src = (const float4*)&A[(size_t)grow * 128 + k];
            float4 v0 = __ldg(src), v1 = __ldg(src + 1);
            uint4 hi, lo;
            hi.x = pk_bf16x2(v0.x, v0.y);
            hi.y = pk_bf16x2(v0.z, v0.w);
            hi.z = pk_bf16x2(v1.x, v1.y);
            hi.w = pk_bf16x2(v1.z, v1.w);
            lo.x = pk_bf16x2(v0.x - __uint_as_float(hi.x << 16), v0.y - __uint_as_float(hi.x & 0xFFFF0000u));
            lo.y = pk_bf16x2(v0.z - __uint_as_float(hi.y << 16), v0.w - __uint_as_float(hi.y & 0xFFFF0000u));
            lo.z = pk_bf16x2(v1.x - __uint_as_float(hi.z << 16), v1.y - __uint_as_float(hi.z & 0xFFFF0000u));
            lo.w = pk_bf16x2(v1.z - __uint_as_float(hi.w << 16), v1.w - __uint_as_float(hi.w & 0xFFFF0000u));
            uint32_t so = swz((uint32_t)row * 256u + (uint32_t)k * 2u);
            *(uint4*)(smem + SM_A + so) = hi;
            *(uint4*)(smem + SM_A + 32768 + so) = lo;
        }
        __syncthreads();

        const int widx = pass ? wr_idx : wl_idx;
        const uint2* bfh = &g_Bfrag[widx][0][0][wn * 8][lane];
        const uint2* bfl = &g_Bfrag[widx][1][0][wn * 8][lane];

#pragma unroll
        for (int kc = 0; kc < 8; kc++) {
            uint32_t ah[2][4], al[2][4];
#pragma unroll
            for (int tm = 0; tm < 2; tm++) {
                uint32_t so = swz(aoff[tm] + (uint32_t)kc * 32u);
                ldm4(ah[tm], sb + SM_A + so);
                ldm4(al[tm], sb + SM_A + 32768 + so);
            }
#pragma unroll
            for (int tn = 0; tn < 8; tn++) {
                uint2 bh = __ldg(bfh + (size_t)kc * 512 + tn * 32);
                uint2 bl = __ldg(bfl + (size_t)kc * 512 + tn * 32);
#pragma unroll
                for (int tm = 0; tm < 2; tm++) {
                    mma16816(acc[tm][tn], ah[tm], bh.x, bh.y);
                    mma16816(acc[tm][tn], ah[tm], bl.x, bl.y);
                    mma16816(acc[tm][tn], al[tm], bh.x, bh.y);
                }
            }
        }
    }

    // ---- epilogue ----
    const int gid = lane >> 2, qid = lane & 3;
#pragma unroll
    for (int tm = 0; tm < 2; tm++) {
#pragma unroll
        for (int rs = 0; rs < 2; rs++) {
            int row = base + wm * 32 + tm * 16 + gid + rs * 8;
            if (row < M) {
#pragma unroll
                for (int tn = 0; tn < 8; tn++) {
                    int col = wn * 64 + tn * 8 + qid * 2;
                    float vx = acc[tm][tn][rs * 2 + 0] + bsm[col];
                    float vy = acc[tm][tn][rs * 2 + 1] + bsm[col + 1];
                    if (mode) {
                        float2 xv = __ldg((const float2*)&xA[(size_t)row * 128 + col]);
                        vx = xv.x + fmaxf(vx, 0.f);
                        vy = xv.y + fmaxf(vy, 0.f);
                    }
                    *(float2*)&out[(size_t)row * 128 + col] = make_float2(vx, vy);
                }
            }
        }
    }
}

// ---------------- host ------------------------------------------------------
extern "C" void kernel_launch(void* const* d_in, const int* in_sizes, int n_in,
                              void* d_out, int out_size)
{
    const float* x_user = nullptr;
    const float* x_movie = nullptr;
    const int* e_src = nullptr;
    const int* e_dst = nullptr;
    const float* W[8] = {};
    const float* B[4] = {};
    int nw = 0, nb = 0;
    for (int i = 0; i < n_in; i++) {
        int sz = in_sizes[i];
        if (sz == NU * DD)      x_user = (const float*)d_in[i];
        else if (sz == NM * DD) x_movie = (const float*)d_in[i];
        else if (sz == EE)      { if (!e_src) e_src = (const int*)d_in[i]; else e_dst = (const int*)d_in[i]; }
        else if (sz == DD * DD) { if (nw < 8) W[nw++] = (const float*)d_in[i]; }
        else if (sz == DD)      { if (nb < 4) B[nb++] = (const float*)d_in[i]; }
    }
    // W order: Wl1_um, Wr1_um, Wl1_mu, Wr1_mu, Wl2_um, Wr2_um, Wl2_mu, Wr2_mu
    const float *b1_um = B[0], *b1_mu = B[1], *b2_um = B[2], *b2_mu = B[3];

    float* out = (float*)d_out;
    float *r_u, *r_m;
    int *deg_u, *deg_m;
    cudaGetSymbolAddress((void**)&r_u, g_r_u);
    cudaGetSymbolAddress((void**)&r_m, g_r_m);
    cudaGetSymbolAddress((void**)&deg_u, g_deg_u);
    cudaGetSymbolAddress((void**)&deg_m, g_deg_m);

    cudaFuncSetAttribute(tgemm_kernel, cudaFuncAttributeMaxDynamicSharedMemorySize, SM_TOTAL);

    const int gb_m = (NM + 127) / 128;
    const int gb_u = (NU + 127) / 128;
    const int gblocks = (NU + NM) / 8;          // one warp per node

    prep_kernel<<<8, 256>>>(W[0], W[1], W[2], W[3], W[4], W[5], W[6], W[7]);

    // CSR build (reused by both layers)
    cudaMemsetAsync(deg_u, 0, NU * sizeof(int));
    cudaMemsetAsync(deg_m, 0, NM * sizeof(int));
    build_kernel<<<(EE + 255) / 256, 256>>>(e_src, e_dst);

    // Layer 1
    gather_kernel<<<gblocks, 256>>>((const float4*)x_user, (const float4*)x_movie);
    tgemm_kernel<<<gb_u + gb_m, 256, SM_TOTAL>>>(x_user, x_movie, b1_mu, b1_um,
                                                 r_u, r_m, gb_u, 1, 0);

    // Layer 2
    gather_kernel<<<gblocks, 256>>>((const float4*)r_u, (const float4*)r_m);
    tgemm_kernel<<<gb_u + gb_m, 256, SM_TOTAL>>>(r_u, r_m, b2_mu, b2_um,
                                                 out, out + (size_t)NU * DD, gb_u, 0, 1);
}